// round 9
// baseline (speedup 1.0000x reference)
#include <cuda_runtime.h>
#include <cstdint>

#define NN 100000
#define EE 1600000
#define D  64
#define MAXDEG 64    // avg degree = 16; P(deg > 64) ~ e^-126, plus runtime clamp
#define NBANDS 6250  // 100000 / 16, exact
#define FGRID 296    // 2 CTAs/SM * 148 SMs
#define WSTRIDE 36   // uint2 per n-row in smem W tiles (conflict-free LDS.64)
#define ASTRIDE 68   // floats per gathered row in smem (16B-aligned, padded)

// Scratch (device globals: allocation-free per harness rules)
__device__ int      g_cnt[NN];
__device__ int      g_csr[(size_t)NN * MAXDEG];
// W pre-packed bf16 fragments: index ((n*8 + chunk)*4 + t4) -> uint2 {b0, b1}
__device__ uint2    g_bhi[64 * 8 * 4];
__device__ uint2    g_blo[64 * 8 * 4];

// ---------------------------------------------------------------------------
// bf16 helpers (plain sm_80+ PTX)
// ---------------------------------------------------------------------------
__device__ __forceinline__ uint32_t pack_bf16(float lo, float hi) {
    uint32_t r;  // PTX cvt packs first source into upper half
    asm("cvt.rn.bf16x2.f32 %0, %1, %2;" : "=r"(r) : "f"(hi), "f"(lo));
    return r;
}
__device__ __forceinline__ void split2_bf16(float f0, float f1,
                                            uint32_t& hi, uint32_t& lo) {
    hi = pack_bf16(f0, f1);
    float h0 = __uint_as_float(hi << 16);
    float h1 = __uint_as_float(hi & 0xffff0000u);
    lo = pack_bf16(f0 - h0, f1 - h1);
}
__device__ __forceinline__ void mma_bf16(float* c, uint32_t a0, uint32_t a1,
                                         uint32_t a2, uint32_t a3,
                                         uint32_t b0, uint32_t b1) {
    asm volatile(
        "mma.sync.aligned.m16n8k16.row.col.f32.bf16.bf16.f32 "
        "{%0,%1,%2,%3}, {%4,%5,%6,%7}, {%8,%9}, {%0,%1,%2,%3};"
        : "+f"(c[0]), "+f"(c[1]), "+f"(c[2]), "+f"(c[3])
        : "r"(a0), "r"(a1), "r"(a2), "r"(a3), "r"(b0), "r"(b1));
}

// ---------------------------------------------------------------------------
// Kernel 1: setup = zero counters + pre-split/pack W fragments
// ---------------------------------------------------------------------------
__global__ void setup_kernel(const float* __restrict__ W) {
    int i = blockIdx.x * blockDim.x + threadIdx.x;
    if (i < NN) g_cnt[i] = 0;
    if (i < 64 * 8 * 4) {
        int t4 = i & 3;
        int c  = (i >> 2) & 7;
        int n  = i >> 5;
        const float* wr = W + n * 128 + c * 16;
        uint32_t h0, l0, h1, l1;
        split2_bf16(wr[2 * t4],     wr[2 * t4 + 1],     h0, l0);
        split2_bf16(wr[8 + 2 * t4], wr[8 + 2 * t4 + 1], h1, l1);
        g_bhi[i] = make_uint2(h0, h1);
        g_blo[i] = make_uint2(l0, l1);
    }
}

// ---------------------------------------------------------------------------
// Kernel 2: bucket edges into padded CSR. 2 edges per thread (int2 loads).
// ---------------------------------------------------------------------------
__global__ void fill_kernel(const int* __restrict__ ei) {
    int t = blockIdx.x * blockDim.x + threadIdx.x;
    if (t * 2 >= EE) return;
    int2 d2 = *(const int2*)(ei + 2 * t);
    int2 s2 = *(const int2*)(ei + EE + 2 * t);
    int p0 = atomicAdd(g_cnt + d2.x, 1);
    if (p0 < MAXDEG) g_csr[(size_t)d2.x * MAXDEG + p0] = s2.x;
    int p1 = atomicAdd(g_cnt + d2.y, 1);
    if (p1 < MAXDEG) g_csr[(size_t)d2.y * MAXDEG + p1] = s2.y;
}

// smem layout (uint32 units)
#define SMU_WHI   0
#define SMU_WLO   (64 * WSTRIDE * 2)
#define SMU_BIAS  (2 * 64 * WSTRIDE * 2)
#define SMU_GAM   (SMU_BIAS + 64)
#define SMU_BET   (SMU_BIAS + 128)
#define SMU_SBUF  (SMU_BIAS + 192)
#define SMU_TOTAL (SMU_SBUF + 8 * 16 * ASTRIDE)   // 8 warps x 16 rows x 68 floats

// ---------------------------------------------------------------------------
// Kernel 3: FUSED persistent gather-mean + mma.sync bf16 GEMM + bias+ReLU+LN.
// 296 CTAs x 8 warps. Per 16-node band, per warp:
//   phase A: mean-aggregate neighbors into warp-private smem rows (2 nodes
//            per LDG.128 step: 16 lanes x float4 per row)
//   phase B: m16n8k16 bf16 3-way-split MMA; A k<64 from x (global),
//            A k>=64 from the smem gather buffer. Epilogue: LN + store.
// ---------------------------------------------------------------------------
__global__ void __launch_bounds__(256, 2)
fused_kernel(const float* __restrict__ x,
             const float* __restrict__ b,
             const float* __restrict__ gamma,
             const float* __restrict__ beta,
             float* __restrict__ out) {
    extern __shared__ uint32_t su[];
    uint2* whi = (uint2*)(su + SMU_WHI);    // [64][WSTRIDE]
    uint2* wlo = (uint2*)(su + SMU_WLO);
    float* bias = (float*)(su + SMU_BIAS);
    float* gam  = (float*)(su + SMU_GAM);
    float* bet  = (float*)(su + SMU_BET);

    const int tid  = threadIdx.x;
    const int wid  = tid >> 5;
    const int lane = tid & 31;

    float* sbuf = (float*)(su + SMU_SBUF) + wid * 16 * ASTRIDE;  // warp-private

    // stage packed W fragments (once per CTA)
    for (int t = tid; t < 64 * 32; t += 256) {
        int n = t >> 5;
        int s = t & 31;
        whi[n * WSTRIDE + s] = g_bhi[n * 32 + s];
        wlo[n * WSTRIDE + s] = g_blo[n * 32 + s];
    }
    if (tid < 64) {
        bias[tid] = b[tid];
        gam[tid]  = gamma[tid];
        bet[tid]  = beta[tid];
    }
    __syncthreads();

    const int g  = lane >> 2;
    const int t4 = lane & 3;
    const int half   = lane >> 4;    // 0/1: which node of the pair (phase A)
    const int lane16 = lane & 15;    // float4 chunk within row   (phase A)
    const int gwarp  = blockIdx.x * 8 + wid;
    const int nwarps = FGRID * 8;

    const float4* x4 = (const float4*)x;

    for (int band = gwarp; band < NBANDS; band += nwarps) {
        // ================= phase A: gather-mean 16 nodes into sbuf ========
        __syncwarp();                       // sbuf reuse fence across bands
#pragma unroll 1
        for (int p = 0; p < 8; p++) {
            int node = band * 16 + 2 * p + half;
            int cnt = g_cnt[node];
            int nloc = min(cnt, MAXDEG);
            int nmax = max(nloc, __shfl_xor_sync(0xffffffffu, nloc, 16));

            const int4* csr4 = (const int4*)(g_csr + (size_t)node * MAXDEG);
            float4 acc = make_float4(0.f, 0.f, 0.f, 0.f);
            for (int i = 0; i < nmax; i += 8) {
                int4 a = csr4[(i >> 2)];
                int4 c = csr4[(i >> 2) + 1];
                float4 v;
                if (i + 0 < nloc) { v = x4[(size_t)a.x * 16 + lane16]; acc.x += v.x; acc.y += v.y; acc.z += v.z; acc.w += v.w; }
                if (i + 1 < nloc) { v = x4[(size_t)a.y * 16 + lane16]; acc.x += v.x; acc.y += v.y; acc.z += v.z; acc.w += v.w; }
                if (i + 2 < nloc) { v = x4[(size_t)a.z * 16 + lane16]; acc.x += v.x; acc.y += v.y; acc.z += v.z; acc.w += v.w; }
                if (i + 3 < nloc) { v = x4[(size_t)a.w * 16 + lane16]; acc.x += v.x; acc.y += v.y; acc.z += v.z; acc.w += v.w; }
                if (i + 4 < nloc) { v = x4[(size_t)c.x * 16 + lane16]; acc.x += v.x; acc.y += v.y; acc.z += v.z; acc.w += v.w; }
                if (i + 5 < nloc) { v = x4[(size_t)c.y * 16 + lane16]; acc.x += v.x; acc.y += v.y; acc.z += v.z; acc.w += v.w; }
                if (i + 6 < nloc) { v = x4[(size_t)c.z * 16 + lane16]; acc.x += v.x; acc.y += v.y; acc.z += v.z; acc.w += v.w; }
                if (i + 7 < nloc) { v = x4[(size_t)c.w * 16 + lane16]; acc.x += v.x; acc.y += v.y; acc.z += v.z; acc.w += v.w; }
            }
            float inv = 1.0f / fmaxf((float)cnt, 1.0f);
            acc.x *= inv; acc.y *= inv; acc.z *= inv; acc.w *= inv;
            *(float4*)(sbuf + (2 * p + half) * ASTRIDE + lane16 * 4) = acc;
        }
        __syncwarp();

        // ================= phase B: MMA + epilogue ========================
        const int node0 = band * 16 + g;          // rows node0, node0+8
        const float* xr0 = x + (size_t)node0 * D;
        const float* xr1 = x + (size_t)(node0 + 8) * D;
        const float* sr0 = sbuf + g * ASTRIDE;
        const float* sr1 = sbuf + (g + 8) * ASTRIDE;

        float acc[32];
#pragma unroll
        for (int i = 0; i < 32; i++) acc[i] = 0.0f;

#pragma unroll
        for (int c = 0; c < 8; c++) {             // k16 chunk; 0-3 x, 4-7 sbuf
            int kb = (c & 3) * 16;
            float2 f00, f01, f10, f11;
            if (c < 4) {
                f00 = *(const float2*)(xr0 + kb + 2 * t4);
                f01 = *(const float2*)(xr0 + kb + 8 + 2 * t4);
                f10 = *(const float2*)(xr1 + kb + 2 * t4);
                f11 = *(const float2*)(xr1 + kb + 8 + 2 * t4);
            } else {
                f00 = *(const float2*)(sr0 + kb + 2 * t4);
                f01 = *(const float2*)(sr0 + kb + 8 + 2 * t4);
                f10 = *(const float2*)(sr1 + kb + 2 * t4);
                f11 = *(const float2*)(sr1 + kb + 8 + 2 * t4);
            }

            uint32_t ah0, al0, ah1, al1, ah2, al2, ah3, al3;
            split2_bf16(f00.x, f00.y, ah0, al0);
            split2_bf16(f10.x, f10.y, ah1, al1);
            split2_bf16(f01.x, f01.y, ah2, al2);
            split2_bf16(f11.x, f11.y, ah3, al3);

#pragma unroll
            for (int nt = 0; nt < 8; nt++) {
                int off = (nt * 8 + g) * WSTRIDE + c * 4 + t4;
                uint2 bh = whi[off];
                uint2 bl = wlo[off];
                float* cc = acc + nt * 4;
                mma_bf16(cc, ah0, ah1, ah2, ah3, bh.x, bh.y);
                mma_bf16(cc, ah0, ah1, ah2, ah3, bl.x, bl.y);
                mma_bf16(cc, al0, al1, al2, al3, bh.x, bh.y);
            }
        }

        // ---- epilogue: bias + ReLU + LayerNorm + store ----
        float v0[16], v1[16];
        float s0 = 0.0f, s1 = 0.0f;
#pragma unroll
        for (int nt = 0; nt < 8; nt++) {
            int col = nt * 8 + 2 * t4;
            float2 bb = *(const float2*)&bias[col];
            float a = fmaxf(acc[nt * 4 + 0] + bb.x, 0.0f);
            float bq = fmaxf(acc[nt * 4 + 1] + bb.y, 0.0f);
            float cq = fmaxf(acc[nt * 4 + 2] + bb.x, 0.0f);
            float dq = fmaxf(acc[nt * 4 + 3] + bb.y, 0.0f);
            v0[nt * 2] = a;  v0[nt * 2 + 1] = bq;
            v1[nt * 2] = cq; v1[nt * 2 + 1] = dq;
            s0 += a + bq;
            s1 += cq + dq;
        }
        s0 += __shfl_xor_sync(0xffffffffu, s0, 1);
        s0 += __shfl_xor_sync(0xffffffffu, s0, 2);
        s1 += __shfl_xor_sync(0xffffffffu, s1, 1);
        s1 += __shfl_xor_sync(0xffffffffu, s1, 2);
        float mu0 = s0 * (1.0f / D), mu1 = s1 * (1.0f / D);

        float ss0 = 0.0f, ss1 = 0.0f;
#pragma unroll
        for (int i = 0; i < 16; i++) {
            float d0 = v0[i] - mu0; ss0 += d0 * d0;
            float d1 = v1[i] - mu1; ss1 += d1 * d1;
        }
        ss0 += __shfl_xor_sync(0xffffffffu, ss0, 1);
        ss0 += __shfl_xor_sync(0xffffffffu, ss0, 2);
        ss1 += __shfl_xor_sync(0xffffffffu, ss1, 1);
        ss1 += __shfl_xor_sync(0xffffffffu, ss1, 2);
        float rs0 = rsqrtf(ss0 * (1.0f / D) + 1e-5f);
        float rs1 = rsqrtf(ss1 * (1.0f / D) + 1e-5f);

        float* o0 = out + (size_t)node0 * D;
        float* o1 = out + (size_t)(node0 + 8) * D;
#pragma unroll
        for (int nt = 0; nt < 8; nt++) {
            int col = nt * 8 + 2 * t4;
            float2 gg = *(const float2*)&gam[col];
            float2 be = *(const float2*)&bet[col];
            float2 w0, w1;
            w0.x = (v0[nt * 2]     - mu0) * rs0 * gg.x + be.x;
            w0.y = (v0[nt * 2 + 1] - mu0) * rs0 * gg.y + be.y;
            w1.x = (v1[nt * 2]     - mu1) * rs1 * gg.x + be.x;
            w1.y = (v1[nt * 2 + 1] - mu1) * rs1 * gg.y + be.y;
            *(float2*)(o0 + col) = w0;
            *(float2*)(o1 + col) = w1;
        }
    }
}

// ---------------------------------------------------------------------------
extern "C" void kernel_launch(void* const* d_in, const int* in_sizes, int n_in,
                              void* d_out, int out_size) {
    const float* x     = (const float*)d_in[0];
    const int*   ei    = (const int*)d_in[1];
    const float* W     = (const float*)d_in[2];
    const float* b     = (const float*)d_in[3];
    const float* gamma = (const float*)d_in[4];
    const float* beta  = (const float*)d_in[5];
    float*       out   = (float*)d_out;

    (void)in_sizes; (void)n_in; (void)out_size;

    const int smem_bytes = SMU_TOTAL * sizeof(uint32_t);   // ~72.4 KB
    cudaFuncSetAttribute(fused_kernel,
                         cudaFuncAttributeMaxDynamicSharedMemorySize, smem_bytes);

    setup_kernel<<<(NN + 255) / 256, 256>>>(W);
    fill_kernel<<<(EE / 2 + 255) / 256, 256>>>(ei);
    fused_kernel<<<FGRID, 256, smem_bytes>>>(x, b, gamma, beta, out);
}

// round 10
// speedup vs baseline: 1.1388x; 1.1388x over previous
#include <cuda_runtime.h>
#include <cstdint>

#define NN 100000
#define EE 1600000
#define D  64
#define MAXDEG 64    // avg degree = 16; P(deg > 64) ~ e^-126, plus runtime clamp
#define NBANDS 6250  // 100000 / 16, exact
#define FGRID 296    // 2 CTAs/SM * 148 SMs
#define WSTRIDE 36   // uint2 per n-row in smem W tiles (conflict-free LDS.64)

// Scratch (device globals: allocation-free per harness rules)
__device__ int      g_cnt[NN];
__device__ int      g_csr[(size_t)NN * MAXDEG];
__device__ float    g_agg[(size_t)NN * D];
__device__ uint32_t g_xb[(size_t)NN * 32];   // x as packed bf16x2 (12.8 MB)
// W pre-packed bf16 fragments: index ((n*8 + chunk)*4 + t4) -> uint2 {b0, b1}
__device__ uint2    g_bhi[64 * 8 * 4];
__device__ uint2    g_blo[64 * 8 * 4];

// ---------------------------------------------------------------------------
// bf16 helpers (plain sm_80+ PTX)
// ---------------------------------------------------------------------------
__device__ __forceinline__ uint32_t pack_bf16(float lo, float hi) {
    uint32_t r;  // first asm source lands in the UPPER half
    asm("cvt.rn.bf16x2.f32 %0, %1, %2;" : "=r"(r) : "f"(hi), "f"(lo));
    return r;
}
__device__ __forceinline__ void split2_bf16(float f0, float f1,
                                            uint32_t& hi, uint32_t& lo) {
    hi = pack_bf16(f0, f1);
    float h0 = __uint_as_float(hi << 16);
    float h1 = __uint_as_float(hi & 0xffff0000u);
    lo = pack_bf16(f0 - h0, f1 - h1);
}
__device__ __forceinline__ void mma_bf16(float* c, uint32_t a0, uint32_t a1,
                                         uint32_t a2, uint32_t a3,
                                         uint32_t b0, uint32_t b1) {
    asm volatile(
        "mma.sync.aligned.m16n8k16.row.col.f32.bf16.bf16.f32 "
        "{%0,%1,%2,%3}, {%4,%5,%6,%7}, {%8,%9}, {%0,%1,%2,%3};"
        : "+f"(c[0]), "+f"(c[1]), "+f"(c[2]), "+f"(c[3])
        : "r"(a0), "r"(a1), "r"(a2), "r"(a3), "r"(b0), "r"(b1));
}

// ---------------------------------------------------------------------------
// Kernel 1: setup = zero counters + pack W fragments + convert x -> bf16x2
// 800K threads; thread i converts one uint4 (8 floats) of x.
// ---------------------------------------------------------------------------
__global__ void setup_kernel(const float* __restrict__ x,
                             const float* __restrict__ W) {
    int i = blockIdx.x * blockDim.x + threadIdx.x;
    if (i < NN) g_cnt[i] = 0;
    if (i < 64 * 8 * 4) {
        int t4 = i & 3;
        int c  = (i >> 2) & 7;
        int n  = i >> 5;
        const float* wr = W + n * 128 + c * 16;
        uint32_t h0, l0, h1, l1;
        split2_bf16(wr[2 * t4],     wr[2 * t4 + 1],     h0, l0);
        split2_bf16(wr[8 + 2 * t4], wr[8 + 2 * t4 + 1], h1, l1);
        g_bhi[i] = make_uint2(h0, h1);
        g_blo[i] = make_uint2(l0, l1);
    }
    if (i < NN * 8) {
        const float4* xr = (const float4*)x + (size_t)i * 2;
        float4 a = xr[0];
        float4 bq = xr[1];
        uint4 o;
        o.x = pack_bf16(a.x, a.y);
        o.y = pack_bf16(a.z, a.w);
        o.z = pack_bf16(bq.x, bq.y);
        o.w = pack_bf16(bq.z, bq.w);
        ((uint4*)g_xb)[i] = o;
    }
}

// ---------------------------------------------------------------------------
// Kernel 2: bucket edges into padded CSR. 2 edges per thread (int2 loads).
// ---------------------------------------------------------------------------
__global__ void fill_kernel(const int* __restrict__ ei) {
    int t = blockIdx.x * blockDim.x + threadIdx.x;
    if (t * 2 >= EE) return;
    int2 d2 = *(const int2*)(ei + 2 * t);
    int2 s2 = *(const int2*)(ei + EE + 2 * t);
    int p0 = atomicAdd(g_cnt + d2.x, 1);
    if (p0 < MAXDEG) g_csr[(size_t)d2.x * MAXDEG + p0] = s2.x;
    int p1 = atomicAdd(g_cnt + d2.y, 1);
    if (p1 < MAXDEG) g_csr[(size_t)d2.y * MAXDEG + p1] = s2.y;
}

// ---------------------------------------------------------------------------
// Kernel 3: mean aggregation from the bf16-packed x copy.
// 4 nodes per warp: 8 lanes x uint4 (16B) per 128B row -> one LDG.128
// warp-instruction per neighbor row; fp32 accumulation.
// ---------------------------------------------------------------------------
__global__ void __launch_bounds__(256)
aggregate_kernel() {
    int warp = (blockIdx.x * blockDim.x + threadIdx.x) >> 5;
    int lane = threadIdx.x & 31;
    const int node = warp * 4 + (lane >> 3);   // NN % 4 == 0
    if (node >= NN) return;
    const int l8 = lane & 7;

    int cnt = g_cnt[node];
    int nloc = min(cnt, MAXDEG);
    int nmax = nloc;
    nmax = max(nmax, __shfl_xor_sync(0xffffffffu, nmax, 8));
    nmax = max(nmax, __shfl_xor_sync(0xffffffffu, nmax, 16));

    const int4* csr4 = (const int4*)(g_csr + (size_t)node * MAXDEG);
    const uint4* xb4 = (const uint4*)g_xb;     // 8 uint4 per row

    float acc[8];
#pragma unroll
    for (int j = 0; j < 8; j++) acc[j] = 0.0f;

#define AGG_ONE(SRC, IDX)                                                    \
    if ((IDX) < nloc) {                                                      \
        uint4 v = xb4[(size_t)(SRC) * 8 + l8];                               \
        acc[0] += __uint_as_float(v.x << 16);                                \
        acc[1] += __uint_as_float(v.x & 0xffff0000u);                        \
        acc[2] += __uint_as_float(v.y << 16);                                \
        acc[3] += __uint_as_float(v.y & 0xffff0000u);                        \
        acc[4] += __uint_as_float(v.z << 16);                                \
        acc[5] += __uint_as_float(v.z & 0xffff0000u);                        \
        acc[6] += __uint_as_float(v.w << 16);                                \
        acc[7] += __uint_as_float(v.w & 0xffff0000u);                        \
    }

    for (int i = 0; i < nmax; i += 8) {
        int4 a = csr4[(i >> 2)];
        int4 c = csr4[(i >> 2) + 1];
        AGG_ONE(a.x, i + 0)
        AGG_ONE(a.y, i + 1)
        AGG_ONE(a.z, i + 2)
        AGG_ONE(a.w, i + 3)
        AGG_ONE(c.x, i + 4)
        AGG_ONE(c.y, i + 5)
        AGG_ONE(c.z, i + 6)
        AGG_ONE(c.w, i + 7)
    }
#undef AGG_ONE

    float inv = 1.0f / fmaxf((float)cnt, 1.0f);
    float* orow = g_agg + (size_t)node * D + l8 * 8;
    float4 o0 = make_float4(acc[0] * inv, acc[1] * inv, acc[2] * inv, acc[3] * inv);
    float4 o1 = make_float4(acc[4] * inv, acc[5] * inv, acc[6] * inv, acc[7] * inv);
    *(float4*)(orow)     = o0;
    *(float4*)(orow + 4) = o1;
}

// smem layout (uint32 units)
#define SMU_WHI   0
#define SMU_WLO   (64 * WSTRIDE * 2)
#define SMU_BIAS  (2 * 64 * WSTRIDE * 2)
#define SMU_GAM   (SMU_BIAS + 64)
#define SMU_BET   (SMU_BIAS + 128)
#define SMU_TOTAL (SMU_BIAS + 192)

// ---------------------------------------------------------------------------
// Kernel 4: persistent mma.sync bf16 (3-way split) fused GEMM+bias+ReLU+LN.
// (R8 structure — known 28.5us)
// ---------------------------------------------------------------------------
__global__ void __launch_bounds__(256, 2)
finalize_mma_kernel(const float* __restrict__ x,
                    const float* __restrict__ b,
                    const float* __restrict__ gamma,
                    const float* __restrict__ beta,
                    float* __restrict__ out) {
    extern __shared__ uint32_t su[];
    uint2* whi = (uint2*)(su + SMU_WHI);    // [64][WSTRIDE]
    uint2* wlo = (uint2*)(su + SMU_WLO);
    float* bias = (float*)(su + SMU_BIAS);
    float* gam  = (float*)(su + SMU_GAM);
    float* bet  = (float*)(su + SMU_BET);

    const int tid  = threadIdx.x;
    const int wid  = tid >> 5;
    const int lane = tid & 31;

    for (int t = tid; t < 64 * 32; t += 256) {
        int n = t >> 5;
        int s = t & 31;
        whi[n * WSTRIDE + s] = g_bhi[n * 32 + s];
        wlo[n * WSTRIDE + s] = g_blo[n * 32 + s];
    }
    if (tid < 64) {
        bias[tid] = b[tid];
        gam[tid]  = gamma[tid];
        bet[tid]  = beta[tid];
    }
    __syncthreads();

    const int g  = lane >> 2;
    const int t4 = lane & 3;
    const int gwarp  = blockIdx.x * 8 + wid;
    const int nwarps = FGRID * 8;

    for (int band = gwarp; band < NBANDS; band += nwarps) {
        const int node0 = band * 16 + g;          // rows node0, node0+8
        const float* xr0 = x + (size_t)node0 * D;
        const float* xr1 = x + (size_t)(node0 + 8) * D;
        const float* ar0 = g_agg + (size_t)node0 * D;
        const float* ar1 = g_agg + (size_t)(node0 + 8) * D;

        float acc[32];
#pragma unroll
        for (int i = 0; i < 32; i++) acc[i] = 0.0f;

#pragma unroll
        for (int c = 0; c < 8; c++) {             // k16 chunk; 0-3 x, 4-7 agg
            const float* r0 = (c < 4) ? xr0 : ar0;
            const float* r1 = (c < 4) ? xr1 : ar1;
            int kb = (c & 3) * 16;
            float2 f00 = *(const float2*)(r0 + kb + 2 * t4);
            float2 f01 = *(const float2*)(r0 + kb + 8 + 2 * t4);
            float2 f10 = *(const float2*)(r1 + kb + 2 * t4);
            float2 f11 = *(const float2*)(r1 + kb + 8 + 2 * t4);

            uint32_t ah0, al0, ah1, al1, ah2, al2, ah3, al3;
            split2_bf16(f00.x, f00.y, ah0, al0);
            split2_bf16(f10.x, f10.y, ah1, al1);
            split2_bf16(f01.x, f01.y, ah2, al2);
            split2_bf16(f11.x, f11.y, ah3, al3);

#pragma unroll
            for (int nt = 0; nt < 8; nt++) {
                int off = (nt * 8 + g) * WSTRIDE + c * 4 + t4;
                uint2 bh = whi[off];
                uint2 bl = wlo[off];
                float* cc = acc + nt * 4;
                mma_bf16(cc, ah0, ah1, ah2, ah3, bh.x, bh.y);
                mma_bf16(cc, ah0, ah1, ah2, ah3, bl.x, bl.y);
                mma_bf16(cc, al0, al1, al2, al3, bh.x, bh.y);
            }
        }

        // ---- epilogue: bias + ReLU + LayerNorm + store ----
        float v0[16], v1[16];
        float s0 = 0.0f, s1 = 0.0f;
#pragma unroll
        for (int nt = 0; nt < 8; nt++) {
            int col = nt * 8 + 2 * t4;
            float2 bb = *(const float2*)&bias[col];
            float a = fmaxf(acc[nt * 4 + 0] + bb.x, 0.0f);
            float bq = fmaxf(acc[nt * 4 + 1] + bb.y, 0.0f);
            float cq = fmaxf(acc[nt * 4 + 2] + bb.x, 0.0f);
            float dq = fmaxf(acc[nt * 4 + 3] + bb.y, 0.0f);
            v0[nt * 2] = a;  v0[nt * 2 + 1] = bq;
            v1[nt * 2] = cq; v1[nt * 2 + 1] = dq;
            s0 += a + bq;
            s1 += cq + dq;
        }
        s0 += __shfl_xor_sync(0xffffffffu, s0, 1);
        s0 += __shfl_xor_sync(0xffffffffu, s0, 2);
        s1 += __shfl_xor_sync(0xffffffffu, s1, 1);
        s1 += __shfl_xor_sync(0xffffffffu, s1, 2);
        float mu0 = s0 * (1.0f / D), mu1 = s1 * (1.0f / D);

        float ss0 = 0.0f, ss1 = 0.0f;
#pragma unroll
        for (int i = 0; i < 16; i++) {
            float d0 = v0[i] - mu0; ss0 += d0 * d0;
            float d1 = v1[i] - mu1; ss1 += d1 * d1;
        }
        ss0 += __shfl_xor_sync(0xffffffffu, ss0, 1);
        ss0 += __shfl_xor_sync(0xffffffffu, ss0, 2);
        ss1 += __shfl_xor_sync(0xffffffffu, ss1, 1);
        ss1 += __shfl_xor_sync(0xffffffffu, ss1, 2);
        float rs0 = rsqrtf(ss0 * (1.0f / D) + 1e-5f);
        float rs1 = rsqrtf(ss1 * (1.0f / D) + 1e-5f);

        float* o0 = out + (size_t)node0 * D;
        float* o1 = out + (size_t)(node0 + 8) * D;
#pragma unroll
        for (int nt = 0; nt < 8; nt++) {
            int col = nt * 8 + 2 * t4;
            float2 gg = *(const float2*)&gam[col];
            float2 be = *(const float2*)&bet[col];
            float2 w0, w1;
            w0.x = (v0[nt * 2]     - mu0) * rs0 * gg.x + be.x;
            w0.y = (v0[nt * 2 + 1] - mu0) * rs0 * gg.y + be.y;
            w1.x = (v1[nt * 2]     - mu1) * rs1 * gg.x + be.x;
            w1.y = (v1[nt * 2 + 1] - mu1) * rs1 * gg.y + be.y;
            *(float2*)(o0 + col) = w0;
            *(float2*)(o1 + col) = w1;
        }
    }
}

// ---------------------------------------------------------------------------
extern "C" void kernel_launch(void* const* d_in, const int* in_sizes, int n_in,
                              void* d_out, int out_size) {
    const float* x     = (const float*)d_in[0];
    const int*   ei    = (const int*)d_in[1];
    const float* W     = (const float*)d_in[2];
    const float* b     = (const float*)d_in[3];
    const float* gamma = (const float*)d_in[4];
    const float* beta  = (const float*)d_in[5];
    float*       out   = (float*)d_out;

    (void)in_sizes; (void)n_in; (void)out_size;

    const int smem_bytes = SMU_TOTAL * sizeof(uint32_t);   // ~37.6 KB
    cudaFuncSetAttribute(finalize_mma_kernel,
                         cudaFuncAttributeMaxDynamicSharedMemorySize, smem_bytes);

    setup_kernel<<<(NN * 8 + 255) / 256, 256>>>(x, W);
    fill_kernel<<<(EE / 2 + 255) / 256, 256>>>(ei);
    aggregate_kernel<<<(NN / 4 * 32 + 255) / 256, 256>>>();   // 4 nodes / warp
    finalize_mma_kernel<<<FGRID, 256, smem_bytes>>>(x, b, gamma, beta, out);
}